// round 1
// baseline (speedup 1.0000x reference)
#include <cuda_runtime.h>
#include <cstddef>

// GloVe loss kernel for GB300 (sm_103a).
// Inputs (metadata order):
//  0: center   int32 [262144,1]
//  1: outside  int32 [262144,1]
//  2: coocs    f32   [262144,1]
//  3: weighting f32  [262144,1]
//  4: center_embedding  f32 [100000,300]
//  5: outside_embedding f32 [100000,300]
//  6: center_bias  f32 [100000,1]
//  7: outside_bias f32 [100000,1]
// Output: scalar f32 loss.

static constexpr int EMB            = 300;
static constexpr int NV4            = EMB / 4;      // 75 float4 per row
static constexpr int BATCH_N        = 262144;
static constexpr int THREADS        = 256;
static constexpr int WARPS_PER_BLK  = THREADS / 32; // 8
static constexpr int ROWS_PER_WARP  = 4;
static constexpr int BLOCKS         = BATCH_N / (WARPS_PER_BLK * ROWS_PER_WARP); // 8192

__device__ double g_acc;

__global__ void glove_zero_kernel() {
    g_acc = 0.0;
}

__global__ __launch_bounds__(THREADS) void glove_main_kernel(
    const int*   __restrict__ center,
    const int*   __restrict__ outside,
    const float* __restrict__ coocs,
    const float* __restrict__ weighting,
    const float* __restrict__ cemb,
    const float* __restrict__ oemb,
    const float* __restrict__ cbias,
    const float* __restrict__ obias)
{
    const int lane  = threadIdx.x & 31;
    const int warp  = threadIdx.x >> 5;
    const int gwarp = blockIdx.x * WARPS_PER_BLK + warp;

    float wsum = 0.0f;

    #pragma unroll
    for (int r = 0; r < ROWS_PER_WARP; ++r) {
        const int row = gwarp * ROWS_PER_WARP + r;

        const int ci = __ldg(center  + row);
        const int oi = __ldg(outside + row);

        const float4* __restrict__ ca = reinterpret_cast<const float4*>(cemb + (size_t)ci * EMB);
        const float4* __restrict__ ob = reinterpret_cast<const float4*>(oemb + (size_t)oi * EMB);

        // 75 float4 per row: lanes 0..31, 32..63, 64..74.
        // Issue all 6 independent LDG.128 up front for MLP.
        float4 a0 = __ldg(ca + lane);
        float4 b0 = __ldg(ob + lane);
        float4 a1 = __ldg(ca + lane + 32);
        float4 b1 = __ldg(ob + lane + 32);
        float4 a2 = make_float4(0.f, 0.f, 0.f, 0.f);
        float4 b2 = make_float4(0.f, 0.f, 0.f, 0.f);
        if (lane < NV4 - 64) {   // lanes 0..10
            a2 = __ldg(ca + lane + 64);
            b2 = __ldg(ob + lane + 64);
        }

        float dot = a0.x * b0.x + a0.y * b0.y + a0.z * b0.z + a0.w * b0.w;
        dot      += a1.x * b1.x + a1.y * b1.y + a1.z * b1.z + a1.w * b1.w;
        dot      += a2.x * b2.x + a2.y * b2.y + a2.z * b2.z + a2.w * b2.w;

        // Warp reduce
        #pragma unroll
        for (int off = 16; off; off >>= 1)
            dot += __shfl_xor_sync(0xffffffffu, dot, off);

        if (lane == 0) {
            const float err = dot + __ldg(cbias + ci) + __ldg(obias + oi) - __ldg(coocs + row);
            wsum += __ldg(weighting + row) * err * err;
        }
    }

    __shared__ float sh[WARPS_PER_BLK];
    if (lane == 0) sh[warp] = wsum;
    __syncthreads();

    if (threadIdx.x == 0) {
        float s = 0.0f;
        #pragma unroll
        for (int i = 0; i < WARPS_PER_BLK; ++i) s += sh[i];
        atomicAdd(&g_acc, (double)s);
    }
}

__global__ void glove_finalize_kernel(float* __restrict__ out) {
    out[0] = (float)g_acc;
}

extern "C" void kernel_launch(void* const* d_in, const int* in_sizes, int n_in,
                              void* d_out, int out_size) {
    const int*   center    = (const int*)  d_in[0];
    const int*   outside   = (const int*)  d_in[1];
    const float* coocs     = (const float*)d_in[2];
    const float* weighting = (const float*)d_in[3];
    const float* cemb      = (const float*)d_in[4];
    const float* oemb      = (const float*)d_in[5];
    const float* cbias     = (const float*)d_in[6];
    const float* obias     = (const float*)d_in[7];
    float* out = (float*)d_out;

    glove_zero_kernel<<<1, 1>>>();
    glove_main_kernel<<<BLOCKS, THREADS>>>(center, outside, coocs, weighting,
                                           cemb, oemb, cbias, obias);
    glove_finalize_kernel<<<1, 1>>>(out);
}